// round 15
// baseline (speedup 1.0000x reference)
#include <cuda_runtime.h>
#include <cuda_bf16.h>
#include <cuda_fp16.h>

#define NN 100000
#define CC 64
#define CAP 128  // per-row bucket capacity (max expected count ~59)
#define CAP_SHIFT 7
#define BUILD_BLOCKS 2048
#define TRANS_BLOCKS 160  // looping transpose blocks, placed in wave 1

// Static scratch (no allocation allowed)
__device__ __align__(256) __half g_Wt[(size_t)NN * CC];  // W^T in fp16 [N, C]
__device__ int g_rowmin;
__device__ int g_counts[NN];                // raw-row edge counts
__device__ int g_bucket[(size_t)NN * CAP];  // per-row col indices

// Fused kernel: bids [0, TRANS_BLOCKS) loop over all transpose tiles and run
// CONCURRENTLY (same first wave) with the atomic-bound build, which occupies
// bids [TRANS_BLOCKS, TRANS_BLOCKS+BUILD_BLOCKS) at full 2048-block concurrency.
__global__ void build_transpose_kernel(const int* __restrict__ ei, int E,
                                       const float* __restrict__ W, int N,
                                       int C) {
    __shared__ float tile[32][33];
    if (blockIdx.x < TRANS_BLOCKS) {
        // ---- transpose path: W [C, N] -> g_Wt [N, C] in fp16, looped ----
        int nblk = (N + 31) / 32;
        int cblk = (C + 31) / 32;
        int ntiles = nblk * cblk;
        int tx = threadIdx.x & 31;
        int ty = threadIdx.x >> 5;  // 0..7
        for (int tb = blockIdx.x; tb < ntiles; tb += TRANS_BLOCKS) {
            int n0 = (tb % nblk) * 32;
            int c0 = (tb / nblk) * 32;
            int n = n0 + tx;
#pragma unroll
            for (int i = 0; i < 32; i += 8) {
                int c = c0 + ty + i;
                if (n < N && c < C) tile[ty + i][tx] = W[(size_t)c * N + n];
            }
            __syncthreads();
            int ct = c0 + tx;
#pragma unroll
            for (int i = 0; i < 32; i += 8) {
                int nt = n0 + ty + i;
                if (nt < N && ct < C)
                    g_Wt[(size_t)nt * CC + ct] = __float2half(tile[tx][ty + i]);
            }
            __syncthreads();  // smem reuse barrier before next tile load
        }
    } else {
        // ---- build path ----
        int bid = blockIdx.x - TRANS_BLOCKS;  // [0, BUILD_BLOCKS)
        int v = 0x7fffffff;
        int E4 = E >> 2;
        const int4* r4 = (const int4*)ei;
        const int4* c4 = (const int4*)(ei + (size_t)E);
        for (long long i = (long long)bid * blockDim.x + threadIdx.x; i < E4;
             i += (long long)BUILD_BLOCKS * blockDim.x) {
            int4 rv = r4[i];
            int4 cv = c4[i];
            v = min(v, min(min(rv.x, rv.y), min(rv.z, rv.w)));
            int p0 = atomicAdd(&g_counts[rv.x], 1);
            if (p0 < CAP) g_bucket[((size_t)rv.x << CAP_SHIFT) + p0] = cv.x;
            int p1 = atomicAdd(&g_counts[rv.y], 1);
            if (p1 < CAP) g_bucket[((size_t)rv.y << CAP_SHIFT) + p1] = cv.y;
            int p2 = atomicAdd(&g_counts[rv.z], 1);
            if (p2 < CAP) g_bucket[((size_t)rv.z << CAP_SHIFT) + p2] = cv.z;
            int p3 = atomicAdd(&g_counts[rv.w], 1);
            if (p3 < CAP) g_bucket[((size_t)rv.w << CAP_SHIFT) + p3] = cv.w;
        }
        long long tid = (long long)bid * blockDim.x + threadIdx.x;
        for (long long i = (long long)E4 * 4 + tid; i < E;
             i += (long long)BUILD_BLOCKS * blockDim.x) {
            int r = ei[i];
            int c = ei[(size_t)E + i];
            v = min(v, r);
            int p = atomicAdd(&g_counts[r], 1);
            if (p < CAP) g_bucket[((size_t)r << CAP_SHIFT) + p] = c;
        }
#pragma unroll
        for (int o = 16; o; o >>= 1)
            v = min(v, __shfl_xor_sync(0xffffffffu, v, o));
        if ((threadIdx.x & 31) == 0) atomicMin(&g_rowmin, v);
    }
}

// 4 rows per warp; 8 lanes per row; each lane owns 8 channels (fp16 LDG.128).
// Full 8-col blocks: shfls/loads executed by ALL lanes (convergent); inactive
// groups gather row 0 harmlessly and skip only the fp32 flush.
__global__ void gather_kernel(float* __restrict__ out,
                              const float* __restrict__ b, int N) {
    int warp = (blockIdx.x * blockDim.x + threadIdx.x) >> 5;
    int lane = threadIdx.x & 31;
    int grp = lane >> 3;  // 0..3 row group within warp
    int sub = lane & 7;   // lane within group
    int row = warp * 4 + grp;
    bool valid = row < N;

    int rmin = g_rowmin;
    int r = row + rmin;
    int cnt = 0;
    size_t start = 0;
    if (valid && r < N) {
        cnt = min(g_counts[r], CAP);
        start = (size_t)r << CAP_SHIFT;
    }

    float acc[8];
#pragma unroll
    for (int k = 0; k < 8; k++) acc[k] = valid ? __ldg(b + sub * 8 + k) : 0.f;

    int nfull = cnt & ~7;  // cols covered by guard-free full blocks
    int nfullm = __reduce_max_sync(0xffffffffu, nfull);

    const __half2 hz = __float2half2_rn(0.f);

    // ---- full blocks: convergent, no per-col guards ----
    for (int base = 0; base < nfullm; base += 8) {
        bool act = base < nfull;
        int myc = act ? g_bucket[start + base + sub] : 0;
        __half2 h0 = hz, h1 = hz, h2 = hz, h3 = hz;
#pragma unroll
        for (int j = 0; j < 8; j++) {
            int c = __shfl_sync(0xffffffffu, myc, j, 8);
            const uint4 raw =
                *reinterpret_cast<const uint4*>(&g_Wt[(size_t)c * CC + sub * 8]);
            h0 = __hadd2(h0, *reinterpret_cast<const __half2*>(&raw.x));
            h1 = __hadd2(h1, *reinterpret_cast<const __half2*>(&raw.y));
            h2 = __hadd2(h2, *reinterpret_cast<const __half2*>(&raw.z));
            h3 = __hadd2(h3, *reinterpret_cast<const __half2*>(&raw.w));
        }
        if (act) {
            float2 f0 = __half22float2(h0);
            float2 f1 = __half22float2(h1);
            float2 f2 = __half22float2(h2);
            float2 f3 = __half22float2(h3);
            acc[0] += f0.x; acc[1] += f0.y;
            acc[2] += f1.x; acc[3] += f1.y;
            acc[4] += f2.x; acc[5] += f2.y;
            acc[6] += f3.x; acc[7] += f3.y;
        }
    }

    // ---- remainder block (0..7 cols): per-col guards, convergent shfl ----
    int rem = cnt - nfull;
    int remm = __reduce_max_sync(0xffffffffu, rem);
    if (remm > 0) {
        int myc = (sub < rem) ? g_bucket[start + nfull + sub] : -1;
        __half2 h0 = hz, h1 = hz, h2 = hz, h3 = hz;
#pragma unroll
        for (int j = 0; j < 8; j++) {
            int c = __shfl_sync(0xffffffffu, myc, j, 8);
            if (c >= 0) {
                const uint4 raw =
                    *reinterpret_cast<const uint4*>(&g_Wt[(size_t)c * CC + sub * 8]);
                h0 = __hadd2(h0, *reinterpret_cast<const __half2*>(&raw.x));
                h1 = __hadd2(h1, *reinterpret_cast<const __half2*>(&raw.y));
                h2 = __hadd2(h2, *reinterpret_cast<const __half2*>(&raw.z));
                h3 = __hadd2(h3, *reinterpret_cast<const __half2*>(&raw.w));
            }
        }
        float2 f0 = __half22float2(h0);
        float2 f1 = __half22float2(h1);
        float2 f2 = __half22float2(h2);
        float2 f3 = __half22float2(h3);
        acc[0] += f0.x; acc[1] += f0.y;
        acc[2] += f1.x; acc[3] += f1.y;
        acc[4] += f2.x; acc[5] += f2.y;
        acc[6] += f3.x; acc[7] += f3.y;
    }

    if (valid) {
        float4* dst = reinterpret_cast<float4*>(&out[(size_t)row * CC + sub * 8]);
        dst[0] = make_float4(acc[0], acc[1], acc[2], acc[3]);
        dst[1] = make_float4(acc[4], acc[5], acc[6], acc[7]);
    }
}

extern "C" void kernel_launch(void* const* d_in, const int* in_sizes, int n_in,
                              void* d_out, int out_size) {
    const int* edge_index = (const int*)d_in[0];  // [2, E] int32
    const float* W = (const float*)d_in[1];       // [C, N]
    const float* b = (const float*)d_in[2];       // [C]
    float* out = (float*)d_out;                   // [N, C]

    int E = in_sizes[0] / 2;
    int C = in_sizes[2];
    int N = in_sizes[1] / C;

    // Graph memset nodes replace the zero kernel: counts -> 0, rowmin -> large.
    // (0x7F7F7F7F > any row index; atomicMin treats it as +inf.)
    void* counts_ptr = nullptr;
    void* rowmin_ptr = nullptr;
    cudaGetSymbolAddress(&counts_ptr, g_counts);
    cudaGetSymbolAddress(&rowmin_ptr, g_rowmin);
    cudaMemsetAsync(counts_ptr, 0, (size_t)N * sizeof(int));
    cudaMemsetAsync(rowmin_ptr, 0x7F, sizeof(int));

    build_transpose_kernel<<<TRANS_BLOCKS + BUILD_BLOCKS, 256>>>(edge_index, E,
                                                                 W, N, C);
    {
        // 4 rows per warp, 8 warps per block -> 32 rows per block
        int rows_per_block = 32;
        int blocks = (N + rows_per_block - 1) / rows_per_block;
        gather_kernel<<<blocks, 256>>>(out, b, N);
    }
}

// round 16
// speedup vs baseline: 1.0336x; 1.0336x over previous
#include <cuda_runtime.h>
#include <cuda_bf16.h>
#include <cuda_fp16.h>

#define NN 100000
#define CC 64
#define CAP 128  // per-row bucket capacity (max expected count ~59)
#define CAP_SHIFT 7
#define BUILD_BLOCKS 2048
#define TRANS_BLOCKS 160  // looping transpose blocks, co-scheduled in wave 1

// Static scratch (no allocation allowed)
__device__ __align__(256) __half g_Wt[(size_t)NN * CC];  // W^T in fp16 [N, C]
__device__ int g_rowmin;
__device__ int g_counts[NN];                // raw-row edge counts
__device__ int g_bucket[(size_t)NN * CAP];  // per-row col indices

// Zero counts + init rowmin. NOTE: this kernel is load-bearing beyond init —
// its 400KB of stores installs g_counts in L2 right before build, keeping
// build's 3.2M atomicAdds at L2 latency (removing it costs ~24us, measured
// three independent times: R12/R13/R15).
__global__ void zero_kernel(int N) {
    int i = blockIdx.x * blockDim.x + threadIdx.x;
    int4* c4 = (int4*)g_counts;
    if (i < N / 4) c4[i] = make_int4(0, 0, 0, 0);
    if (i == 0) {
        g_rowmin = 0x7fffffff;
        for (int k = (N / 4) * 4; k < N; k++) g_counts[k] = 0;
    }
}

// Fused kernel: bids [0, TRANS_BLOCKS) loop over all transpose tiles and run
// CONCURRENTLY (same first wave) with the atomic-bound build, which occupies
// bids [TRANS_BLOCKS, TRANS_BLOCKS+BUILD_BLOCKS) at full 2048-block concurrency.
__global__ void build_transpose_kernel(const int* __restrict__ ei, int E,
                                       const float* __restrict__ W, int N,
                                       int C) {
    __shared__ float tile[32][33];
    if (blockIdx.x < TRANS_BLOCKS) {
        // ---- transpose path: W [C, N] -> g_Wt [N, C] in fp16, looped ----
        int nblk = (N + 31) / 32;
        int cblk = (C + 31) / 32;
        int ntiles = nblk * cblk;
        int tx = threadIdx.x & 31;
        int ty = threadIdx.x >> 5;  // 0..7
        for (int tb = blockIdx.x; tb < ntiles; tb += TRANS_BLOCKS) {
            int n0 = (tb % nblk) * 32;
            int c0 = (tb / nblk) * 32;
            int n = n0 + tx;
#pragma unroll
            for (int i = 0; i < 32; i += 8) {
                int c = c0 + ty + i;
                if (n < N && c < C) tile[ty + i][tx] = W[(size_t)c * N + n];
            }
            __syncthreads();
            int ct = c0 + tx;
#pragma unroll
            for (int i = 0; i < 32; i += 8) {
                int nt = n0 + ty + i;
                if (nt < N && ct < C)
                    g_Wt[(size_t)nt * CC + ct] = __float2half(tile[tx][ty + i]);
            }
            __syncthreads();  // smem reuse barrier before next tile load
        }
    } else {
        // ---- build path ----
        int bid = blockIdx.x - TRANS_BLOCKS;  // [0, BUILD_BLOCKS)
        int v = 0x7fffffff;
        int E4 = E >> 2;
        const int4* r4 = (const int4*)ei;
        const int4* c4 = (const int4*)(ei + (size_t)E);
        for (long long i = (long long)bid * blockDim.x + threadIdx.x; i < E4;
             i += (long long)BUILD_BLOCKS * blockDim.x) {
            int4 rv = r4[i];
            int4 cv = c4[i];
            v = min(v, min(min(rv.x, rv.y), min(rv.z, rv.w)));
            int p0 = atomicAdd(&g_counts[rv.x], 1);
            if (p0 < CAP) g_bucket[((size_t)rv.x << CAP_SHIFT) + p0] = cv.x;
            int p1 = atomicAdd(&g_counts[rv.y], 1);
            if (p1 < CAP) g_bucket[((size_t)rv.y << CAP_SHIFT) + p1] = cv.y;
            int p2 = atomicAdd(&g_counts[rv.z], 1);
            if (p2 < CAP) g_bucket[((size_t)rv.z << CAP_SHIFT) + p2] = cv.z;
            int p3 = atomicAdd(&g_counts[rv.w], 1);
            if (p3 < CAP) g_bucket[((size_t)rv.w << CAP_SHIFT) + p3] = cv.w;
        }
        long long tid = (long long)bid * blockDim.x + threadIdx.x;
        for (long long i = (long long)E4 * 4 + tid; i < E;
             i += (long long)BUILD_BLOCKS * blockDim.x) {
            int r = ei[i];
            int c = ei[(size_t)E + i];
            v = min(v, r);
            int p = atomicAdd(&g_counts[r], 1);
            if (p < CAP) g_bucket[((size_t)r << CAP_SHIFT) + p] = c;
        }
#pragma unroll
        for (int o = 16; o; o >>= 1)
            v = min(v, __shfl_xor_sync(0xffffffffu, v, o));
        if ((threadIdx.x & 31) == 0) atomicMin(&g_rowmin, v);
    }
}

// 4 rows per warp; 8 lanes per row; each lane owns 8 channels (fp16 LDG.128).
// Full 8-col blocks: shfls/loads executed by ALL lanes (convergent); inactive
// groups gather row 0 harmlessly and skip only the fp32 flush.
__global__ void gather_kernel(float* __restrict__ out,
                              const float* __restrict__ b, int N) {
    int warp = (blockIdx.x * blockDim.x + threadIdx.x) >> 5;
    int lane = threadIdx.x & 31;
    int grp = lane >> 3;  // 0..3 row group within warp
    int sub = lane & 7;   // lane within group
    int row = warp * 4 + grp;
    bool valid = row < N;

    int rmin = g_rowmin;
    int r = row + rmin;
    int cnt = 0;
    size_t start = 0;
    if (valid && r < N) {
        cnt = min(g_counts[r], CAP);
        start = (size_t)r << CAP_SHIFT;
    }

    float acc[8];
#pragma unroll
    for (int k = 0; k < 8; k++) acc[k] = valid ? __ldg(b + sub * 8 + k) : 0.f;

    int nfull = cnt & ~7;  // cols covered by guard-free full blocks
    int nfullm = __reduce_max_sync(0xffffffffu, nfull);

    const __half2 hz = __float2half2_rn(0.f);

    // ---- full blocks: convergent, no per-col guards ----
    for (int base = 0; base < nfullm; base += 8) {
        bool act = base < nfull;
        int myc = act ? g_bucket[start + base + sub] : 0;
        __half2 h0 = hz, h1 = hz, h2 = hz, h3 = hz;
#pragma unroll
        for (int j = 0; j < 8; j++) {
            int c = __shfl_sync(0xffffffffu, myc, j, 8);
            const uint4 raw =
                *reinterpret_cast<const uint4*>(&g_Wt[(size_t)c * CC + sub * 8]);
            h0 = __hadd2(h0, *reinterpret_cast<const __half2*>(&raw.x));
            h1 = __hadd2(h1, *reinterpret_cast<const __half2*>(&raw.y));
            h2 = __hadd2(h2, *reinterpret_cast<const __half2*>(&raw.z));
            h3 = __hadd2(h3, *reinterpret_cast<const __half2*>(&raw.w));
        }
        if (act) {
            float2 f0 = __half22float2(h0);
            float2 f1 = __half22float2(h1);
            float2 f2 = __half22float2(h2);
            float2 f3 = __half22float2(h3);
            acc[0] += f0.x; acc[1] += f0.y;
            acc[2] += f1.x; acc[3] += f1.y;
            acc[4] += f2.x; acc[5] += f2.y;
            acc[6] += f3.x; acc[7] += f3.y;
        }
    }

    // ---- remainder block (0..7 cols): per-col guards, convergent shfl ----
    int rem = cnt - nfull;
    int remm = __reduce_max_sync(0xffffffffu, rem);
    if (remm > 0) {
        int myc = (sub < rem) ? g_bucket[start + nfull + sub] : -1;
        __half2 h0 = hz, h1 = hz, h2 = hz, h3 = hz;
#pragma unroll
        for (int j = 0; j < 8; j++) {
            int c = __shfl_sync(0xffffffffu, myc, j, 8);
            if (c >= 0) {
                const uint4 raw =
                    *reinterpret_cast<const uint4*>(&g_Wt[(size_t)c * CC + sub * 8]);
                h0 = __hadd2(h0, *reinterpret_cast<const __half2*>(&raw.x));
                h1 = __hadd2(h1, *reinterpret_cast<const __half2*>(&raw.y));
                h2 = __hadd2(h2, *reinterpret_cast<const __half2*>(&raw.z));
                h3 = __hadd2(h3, *reinterpret_cast<const __half2*>(&raw.w));
            }
        }
        float2 f0 = __half22float2(h0);
        float2 f1 = __half22float2(h1);
        float2 f2 = __half22float2(h2);
        float2 f3 = __half22float2(h3);
        acc[0] += f0.x; acc[1] += f0.y;
        acc[2] += f1.x; acc[3] += f1.y;
        acc[4] += f2.x; acc[5] += f2.y;
        acc[6] += f3.x; acc[7] += f3.y;
    }

    if (valid) {
        float4* dst = reinterpret_cast<float4*>(&out[(size_t)row * CC + sub * 8]);
        dst[0] = make_float4(acc[0], acc[1], acc[2], acc[3]);
        dst[1] = make_float4(acc[4], acc[5], acc[6], acc[7]);
    }
}

extern "C" void kernel_launch(void* const* d_in, const int* in_sizes, int n_in,
                              void* d_out, int out_size) {
    const int* edge_index = (const int*)d_in[0];  // [2, E] int32
    const float* W = (const float*)d_in[1];       // [C, N]
    const float* b = (const float*)d_in[2];       // [C]
    float* out = (float*)d_out;                   // [N, C]

    int E = in_sizes[0] / 2;
    int C = in_sizes[2];
    int N = in_sizes[1] / C;

    zero_kernel<<<(N / 4 + 255) / 256, 256>>>(N);
    build_transpose_kernel<<<TRANS_BLOCKS + BUILD_BLOCKS, 256>>>(edge_index, E,
                                                                 W, N, C);
    {
        // 4 rows per warp, 8 warps per block -> 32 rows per block
        int rows_per_block = 32;
        int blocks = (N + rows_per_block - 1) / rows_per_block;
        gather_kernel<<<blocks, 256>>>(out, b, N);
    }
}

// round 17
// speedup vs baseline: 1.1351x; 1.0981x over previous
#include <cuda_runtime.h>
#include <cuda_bf16.h>
#include <cuda_fp16.h>

#define NN 100000
#define CC 64
#define CAP 128  // per-row bucket capacity (max expected count ~59)
#define CAP_SHIFT 7
#define TPB 256

// Static scratch (no allocation allowed)
__device__ __align__(256) __half g_Wt[(size_t)NN * CC];  // W^T in fp16 [N, C]
__device__ int g_rowmin;
__device__ int g_counts[NN];                // raw-row edge counts
__device__ int g_bucket[(size_t)NN * CAP];  // per-row col indices
__device__ unsigned g_bar_gen = 0;          // barrier generation (monotonic)
__device__ unsigned g_bar_cnt = 0;          // barrier arrival count

// Sense-reversing grid barrier. Safe only because the launch sizes the grid
// to guaranteed-co-resident blocks (occupancy API x SM count).
// Poll via ld.cg (L2) + nanosleep: atomic-RMW polling would serialize the
// release behind hundreds of queued RMWs on one L2 slice.
__device__ __forceinline__ void grid_barrier(int nblocks) {
    __syncthreads();
    if (threadIdx.x == 0) {
        __threadfence();  // publish this block's phase writes
        unsigned gen = __ldcg(&g_bar_gen);
        unsigned t = atomicAdd(&g_bar_cnt, 1u);
        if (t == (unsigned)(nblocks - 1)) {
            atomicExch(&g_bar_cnt, 0u);
            __threadfence();
            atomicAdd(&g_bar_gen, 1u);  // release
        } else {
            while (__ldcg(&g_bar_gen) == gen) __nanosleep(64);
        }
        __threadfence();  // acquire
    }
    __syncthreads();
}

__global__ void __launch_bounds__(TPB, 4) fused_kernel(
    const int* __restrict__ ei, int E, const float* __restrict__ W,
    const float* __restrict__ b, float* __restrict__ out, int N, int C,
    int nblocks) {
    __shared__ float tile[32][33];
    int tid = threadIdx.x;
    long long gtid = (long long)blockIdx.x * TPB + tid;
    long long gstride = (long long)nblocks * TPB;

    // ---- phase 0: zero counts + rowmin init + transpose W -> fp16 ----
    {
        int n4 = N >> 2;
        int4* c4 = (int4*)g_counts;
        for (long long i = gtid; i < n4; i += gstride)
            c4[i] = make_int4(0, 0, 0, 0);
        if (gtid == 0) {
            g_rowmin = 0x7fffffff;
            for (int k = (N >> 2) << 2; k < N; k++) g_counts[k] = 0;
        }
        int nblk = (N + 31) / 32;
        int cblk = (C + 31) / 32;
        int ntiles = nblk * cblk;
        int tx = tid & 31, ty = tid >> 5;
        for (int tb = blockIdx.x; tb < ntiles; tb += nblocks) {
            int n0 = (tb % nblk) * 32;
            int c0 = (tb / nblk) * 32;
            int n = n0 + tx;
#pragma unroll
            for (int i = 0; i < 32; i += 8) {
                int c = c0 + ty + i;
                if (n < N && c < C) tile[ty + i][tx] = W[(size_t)c * N + n];
            }
            __syncthreads();
            int ct = c0 + tx;
#pragma unroll
            for (int i = 0; i < 32; i += 8) {
                int nt = n0 + ty + i;
                if (nt < N && ct < C)
                    g_Wt[(size_t)nt * CC + ct] = __float2half(tile[tx][ty + i]);
            }
            __syncthreads();
        }
    }
    grid_barrier(nblocks);

    // ---- phase 1: build (bucket-scatter + row min) ----
    {
        int v = 0x7fffffff;
        int E4 = E >> 2;
        const int4* r4 = (const int4*)ei;
        const int4* c4e = (const int4*)(ei + (size_t)E);
        for (long long i = gtid; i < E4; i += gstride) {
            int4 rv = r4[i];
            int4 cv = c4e[i];
            v = min(v, min(min(rv.x, rv.y), min(rv.z, rv.w)));
            int p0 = atomicAdd(&g_counts[rv.x], 1);
            if (p0 < CAP) g_bucket[((size_t)rv.x << CAP_SHIFT) + p0] = cv.x;
            int p1 = atomicAdd(&g_counts[rv.y], 1);
            if (p1 < CAP) g_bucket[((size_t)rv.y << CAP_SHIFT) + p1] = cv.y;
            int p2 = atomicAdd(&g_counts[rv.z], 1);
            if (p2 < CAP) g_bucket[((size_t)rv.z << CAP_SHIFT) + p2] = cv.z;
            int p3 = atomicAdd(&g_counts[rv.w], 1);
            if (p3 < CAP) g_bucket[((size_t)rv.w << CAP_SHIFT) + p3] = cv.w;
        }
        for (long long i = (long long)E4 * 4 + gtid; i < E; i += gstride) {
            int r = ei[i];
            int c = ei[(size_t)E + i];
            v = min(v, r);
            int p = atomicAdd(&g_counts[r], 1);
            if (p < CAP) g_bucket[((size_t)r << CAP_SHIFT) + p] = c;
        }
#pragma unroll
        for (int o = 16; o; o >>= 1)
            v = min(v, __shfl_xor_sync(0xffffffffu, v, o));
        if ((tid & 31) == 0) atomicMin(&g_rowmin, v);
    }
    grid_barrier(nblocks);

    // ---- phase 2: gather (identical math to the 90.6us kernel) ----
    // Cross-block data (rowmin/counts/bucket) read via __ldcg: L1 is NOT
    // flushed intra-kernel, so plain loads could see stale pre-build lines.
    {
        int wid = (int)(gtid >> 5);
        int lane = tid & 31;
        int grp = lane >> 3;  // 0..3 row group within warp
        int sub = lane & 7;   // lane within group
        int nwarps = nblocks * (TPB / 32);
        int rmin = __ldcg(&g_rowmin);
        const __half2 hz = __float2half2_rn(0.f);

        float bias[8];
#pragma unroll
        for (int k = 0; k < 8; k++) bias[k] = __ldg(b + sub * 8 + k);

        for (int row0 = wid * 4; row0 < N; row0 += nwarps * 4) {
            int row = row0 + grp;
            bool valid = row < N;
            int r = row + rmin;
            int cnt = 0;
            size_t start = 0;
            if (valid && r < N) {
                cnt = min(__ldcg(&g_counts[r]), CAP);
                start = (size_t)r << CAP_SHIFT;
            }

            float acc[8];
#pragma unroll
            for (int k = 0; k < 8; k++) acc[k] = valid ? bias[k] : 0.f;

            int nfull = cnt & ~7;
            int nfullm = __reduce_max_sync(0xffffffffu, nfull);

            // full blocks: convergent, no per-col guards
            for (int base = 0; base < nfullm; base += 8) {
                bool act = base < nfull;
                int myc = act ? __ldcg(&g_bucket[start + base + sub]) : 0;
                __half2 h0 = hz, h1 = hz, h2 = hz, h3 = hz;
#pragma unroll
                for (int j = 0; j < 8; j++) {
                    int c = __shfl_sync(0xffffffffu, myc, j, 8);
                    const uint4 raw = *reinterpret_cast<const uint4*>(
                        &g_Wt[(size_t)c * CC + sub * 8]);
                    h0 = __hadd2(h0, *reinterpret_cast<const __half2*>(&raw.x));
                    h1 = __hadd2(h1, *reinterpret_cast<const __half2*>(&raw.y));
                    h2 = __hadd2(h2, *reinterpret_cast<const __half2*>(&raw.z));
                    h3 = __hadd2(h3, *reinterpret_cast<const __half2*>(&raw.w));
                }
                if (act) {
                    float2 f0 = __half22float2(h0);
                    float2 f1 = __half22float2(h1);
                    float2 f2 = __half22float2(h2);
                    float2 f3 = __half22float2(h3);
                    acc[0] += f0.x; acc[1] += f0.y;
                    acc[2] += f1.x; acc[3] += f1.y;
                    acc[4] += f2.x; acc[5] += f2.y;
                    acc[6] += f3.x; acc[7] += f3.y;
                }
            }

            // remainder block: per-col guards, convergent shfl
            int rem = cnt - nfull;
            int remm = __reduce_max_sync(0xffffffffu, rem);
            if (remm > 0) {
                int myc = (sub < rem) ? __ldcg(&g_bucket[start + nfull + sub]) : -1;
                __half2 h0 = hz, h1 = hz, h2 = hz, h3 = hz;
#pragma unroll
                for (int j = 0; j < 8; j++) {
                    int c = __shfl_sync(0xffffffffu, myc, j, 8);
                    if (c >= 0) {
                        const uint4 raw = *reinterpret_cast<const uint4*>(
                            &g_Wt[(size_t)c * CC + sub * 8]);
                        h0 = __hadd2(h0, *reinterpret_cast<const __half2*>(&raw.x));
                        h1 = __hadd2(h1, *reinterpret_cast<const __half2*>(&raw.y));
                        h2 = __hadd2(h2, *reinterpret_cast<const __half2*>(&raw.z));
                        h3 = __hadd2(h3, *reinterpret_cast<const __half2*>(&raw.w));
                    }
                }
                float2 f0 = __half22float2(h0);
                float2 f1 = __half22float2(h1);
                float2 f2 = __half22float2(h2);
                float2 f3 = __half22float2(h3);
                acc[0] += f0.x; acc[1] += f0.y;
                acc[2] += f1.x; acc[3] += f1.y;
                acc[4] += f2.x; acc[5] += f2.y;
                acc[6] += f3.x; acc[7] += f3.y;
            }

            if (valid) {
                float4* dst =
                    reinterpret_cast<float4*>(&out[(size_t)row * CC + sub * 8]);
                dst[0] = make_float4(acc[0], acc[1], acc[2], acc[3]);
                dst[1] = make_float4(acc[4], acc[5], acc[6], acc[7]);
            }
        }
    }
}

extern "C" void kernel_launch(void* const* d_in, const int* in_sizes, int n_in,
                              void* d_out, int out_size) {
    const int* edge_index = (const int*)d_in[0];  // [2, E] int32
    const float* W = (const float*)d_in[1];       // [C, N]
    const float* b = (const float*)d_in[2];       // [C]
    float* out = (float*)d_out;                   // [N, C]

    int E = in_sizes[0] / 2;
    int C = in_sizes[2];
    int N = in_sizes[1] / C;

    // Guaranteed-co-resident grid: occupancy API x SM count. This makes the
    // software grid barrier deadlock-free by construction.
    int dev = 0;
    cudaGetDevice(&dev);
    int nsm = 0;
    cudaDeviceGetAttribute(&nsm, cudaDevAttrMultiProcessorCount, dev);
    int maxb = 0;
    cudaOccupancyMaxActiveBlocksPerMultiprocessor(&maxb, fused_kernel, TPB, 0);
    if (nsm <= 0) nsm = 148;
    if (maxb <= 0) maxb = 1;
    int nblocks = nsm * maxb;
    if (nblocks > 2048) nblocks = 2048;

    fused_kernel<<<nblocks, TPB>>>(edge_index, E, W, b, out, N, C, nblocks);
}